// round 1
// baseline (speedup 1.0000x reference)
#include <cuda_runtime.h>
#include <math.h>

#define HH 134
#define WW 20
#define HW 2680
#define CC 64
#define BB 128
#define NIN 21440       // CC*HW/8
#define GPC 335         // 8-element groups per channel plane (2680/8)

// Scratch (static device globals; no runtime allocation)
__device__ float d_h0[(size_t)BB * CC * HW];   // conv+relu output, 87.8 MB
__device__ float d_sum[BB * CC];
__device__ float d_max[BB * CC];
__device__ float d_ca[BB * CC];
__device__ float d_sa[BB * HW];

// ---------------------------------------------------------------------------
// K1: 3x3 conv (1->64) + ReLU, write h0, per-(b,c) sum & max for channel attn
// grid: (CC, BB), block: 256
// ---------------------------------------------------------------------------
__global__ void k_conv(const float* __restrict__ x,
                       const float* __restrict__ cw,
                       const float* __restrict__ cb) {
    __shared__ float xs[HW];
    __shared__ float rs[8], rm[8];
    const int c = blockIdx.x, b = blockIdx.y, tid = threadIdx.x;
    const int warp = tid >> 5, lane = tid & 31;

    const float* xp = x + (size_t)b * HW;
    for (int p = tid; p < HW; p += 256) xs[p] = xp[p];

    float wt[9];
#pragma unroll
    for (int i = 0; i < 9; i++) wt[i] = cw[c * 9 + i];
    const float bias = cb[c];
    __syncthreads();

    float lsum = 0.f, lmax = -1e30f;
    float* out = d_h0 + ((size_t)b * CC + c) * HW;
    for (int p = tid; p < HW; p += 256) {
        const int hh = p / WW, ww = p - hh * WW;
        float acc = bias;
#pragma unroll
        for (int kh = 0; kh < 3; kh++) {
            const int ih = hh + kh - 1;
            if ((unsigned)ih >= HH) continue;
#pragma unroll
            for (int kw = 0; kw < 3; kw++) {
                const int iw = ww + kw - 1;
                if ((unsigned)iw >= WW) continue;
                acc += xs[ih * WW + iw] * wt[kh * 3 + kw];
            }
        }
        acc = fmaxf(acc, 0.f);
        out[p] = acc;
        lsum += acc;
        lmax = fmaxf(lmax, acc);
    }
#pragma unroll
    for (int off = 16; off; off >>= 1) {
        lsum += __shfl_down_sync(0xffffffffu, lsum, off);
        lmax = fmaxf(lmax, __shfl_down_sync(0xffffffffu, lmax, off));
    }
    if (lane == 0) { rs[warp] = lsum; rm[warp] = lmax; }
    __syncthreads();
    if (tid == 0) {
        float s = 0.f, m = -1e30f;
#pragma unroll
        for (int i = 0; i < 8; i++) { s += rs[i]; m = fmaxf(m, rm[i]); }
        d_sum[b * CC + c] = s;
        d_max[b * CC + c] = m;
    }
}

// ---------------------------------------------------------------------------
// K2: channel attention MLP. grid: BB, block: 64
// ca = sigmoid( relu(avg@W1^T)@W2^T + relu(max@W1^T)@W2^T )
// ---------------------------------------------------------------------------
__global__ void k_ca(const float* __restrict__ w1, const float* __restrict__ w2) {
    __shared__ float avg[CC], mx[CC], hid[8];
    const int b = blockIdx.x, tid = threadIdx.x;  // 64 threads
    avg[tid] = d_sum[b * CC + tid] * (1.f / (float)HW);
    mx[tid] = d_max[b * CC + tid];
    __syncthreads();
    if (tid < 8) {
        const int i = tid & 3;
        const float* v = (tid < 4) ? avg : mx;
        float a = 0.f;
        for (int c = 0; c < CC; c++) a += v[c] * w1[i * CC + c];
        hid[tid] = fmaxf(a, 0.f);
    }
    __syncthreads();
    float o = 0.f;
#pragma unroll
    for (int i = 0; i < 4; i++) o += (hid[i] + hid[4 + i]) * w2[tid * 4 + i];
    d_ca[b * CC + tid] = 1.f / (1.f + __expf(-o));
}

// ---------------------------------------------------------------------------
// K3: spatial attention. grid: BB, block: 512
// sp = [mean_c(h*ca), max_c(h*ca)]; sa = sigmoid(conv7x7(sp))
// ---------------------------------------------------------------------------
__global__ void k_spatial(const float* __restrict__ sw) {
    __shared__ float spm[HW], spx[HW];
    __shared__ float cas[CC], ws[98];
    const int b = blockIdx.x, tid = threadIdx.x;  // 512 threads
    if (tid < CC) cas[tid] = d_ca[b * CC + tid];
    if (tid >= 128 && tid < 128 + 98) ws[tid - 128] = sw[tid - 128];
    __syncthreads();
    const float* hp = d_h0 + (size_t)b * CC * HW;
    for (int p = tid; p < HW; p += 512) {
        float s = 0.f, m = -1e30f;
#pragma unroll 8
        for (int c = 0; c < CC; c++) {
            const float v = hp[(size_t)c * HW + p] * cas[c];
            s += v;
            m = fmaxf(m, v);
        }
        spm[p] = s * (1.f / (float)CC);
        spx[p] = m;
    }
    __syncthreads();
    for (int p = tid; p < HW; p += 512) {
        const int hh = p / WW, ww = p - hh * WW;
        float acc = 0.f;
#pragma unroll
        for (int kh = 0; kh < 7; kh++) {
            const int ih = hh + kh - 3;
            if ((unsigned)ih >= HH) continue;
#pragma unroll
            for (int kw = 0; kw < 7; kw++) {
                const int iw = ww + kw - 3;
                if ((unsigned)iw >= WW) continue;
                const int q = ih * WW + iw;
                acc += spm[q] * ws[kh * 7 + kw] + spx[q] * ws[49 + kh * 7 + kw];
            }
        }
        d_sa[b * HW + p] = 1.f / (1.f + __expf(-acc));
    }
}

// ---------------------------------------------------------------------------
// K4: dynamic routing, fully block-local per batch. grid: BB, block: 512
// b[j,n] = u_n . g_j  (g_j accumulates W^T v across iterations), so routing
// needs only 3 streaming passes over u = h0*ca*sa (applied on the fly).
// ---------------------------------------------------------------------------
__global__ void k_routing(const float* __restrict__ capsW, float* __restrict__ out) {
    __shared__ float sas[HW];      // sa plane
    __shared__ float cas[CC];
    __shared__ float Ws[8 * 32];   // caps_W, row-major [k][e]
    __shared__ float red[16 * 16]; // per-warp partials of sc
    __shared__ float sc[16];       // sc[j*8+k] = sum_n c_j * u_n[k]
    __shared__ float ss[32], vs[32];
    __shared__ float g[16];        // g[j*8+k]
    const int b = blockIdx.x, tid = threadIdx.x;  // 512 threads
    const int warp = tid >> 5, lane = tid & 31;

    for (int p = tid; p < HW; p += 512) sas[p] = d_sa[b * HW + p];
    if (tid < CC) cas[tid] = d_ca[b * CC + tid];
    if (tid < 256) Ws[tid] = capsW[tid];
    if (tid < 16) g[tid] = 0.f;
    __syncthreads();

    const float* hp = d_h0 + (size_t)b * CC * HW;

    for (int iter = 0; iter < 3; iter++) {
        float gd[8];
#pragma unroll
        for (int k = 0; k < 8; k++) gd[k] = g[k] - g[8 + k];
        float a0[8], a1[8];
#pragma unroll
        for (int k = 0; k < 8; k++) { a0[k] = 0.f; a1[k] = 0.f; }

        for (int n = tid; n < NIN; n += 512) {
            const int cix = n / GPC;
            const int pos = (n - cix * GPC) * 8;
            const float4* up = (const float4*)(hp + (size_t)n * 8);
            const float4 r0 = up[0];
            const float4 r1 = up[1];
            const float cav = cas[cix];
            float u[8];
            u[0] = r0.x * cav * sas[pos + 0];
            u[1] = r0.y * cav * sas[pos + 1];
            u[2] = r0.z * cav * sas[pos + 2];
            u[3] = r0.w * cav * sas[pos + 3];
            u[4] = r1.x * cav * sas[pos + 4];
            u[5] = r1.y * cav * sas[pos + 5];
            u[6] = r1.z * cav * sas[pos + 6];
            u[7] = r1.w * cav * sas[pos + 7];
            float d = 0.f;
#pragma unroll
            for (int k = 0; k < 8; k++) d += u[k] * gd[k];
            const float c0 = 1.f / (1.f + __expf(-d));   // softmax over J=2
            const float c1 = 1.f - c0;
#pragma unroll
            for (int k = 0; k < 8; k++) { a0[k] += c0 * u[k]; a1[k] += c1 * u[k]; }
        }

        // block reduce 16 accumulators
#pragma unroll
        for (int k = 0; k < 8; k++) {
#pragma unroll
            for (int off = 16; off; off >>= 1) {
                a0[k] += __shfl_down_sync(0xffffffffu, a0[k], off);
                a1[k] += __shfl_down_sync(0xffffffffu, a1[k], off);
            }
        }
        if (lane == 0) {
#pragma unroll
            for (int k = 0; k < 8; k++) {
                red[warp * 16 + k] = a0[k];
                red[warp * 16 + 8 + k] = a1[k];
            }
        }
        __syncthreads();
        if (tid < 16) {
            float s = 0.f;
#pragma unroll
            for (int w = 0; w < 16; w++) s += red[w * 16 + tid];
            sc[tid] = s;
        }
        __syncthreads();
        // s[j][d] = sum_k sc[j][k] * W[k][j*16+d]
        if (tid < 32) {
            const int j = tid >> 4;
            float s = 0.f;
#pragma unroll
            for (int k = 0; k < 8; k++) s += sc[j * 8 + k] * Ws[k * 32 + tid];
            ss[tid] = s;
        }
        __syncthreads();
        // squash per capsule j
        if (tid < 32) {
            const int j = tid >> 4;
            float s2 = 1e-8f;
#pragma unroll
            for (int dd = 0; dd < 16; dd++) { const float t = ss[j * 16 + dd]; s2 += t * t; }
            vs[tid] = (sqrtf(s2) / (1.f + s2)) * ss[tid];
        }
        __syncthreads();
        // g_j[k] += sum_d v[j][d] * W[k][j*16+d]
        if (tid < 16) {
            const int j = tid >> 3, k = tid & 7;
            float a = 0.f;
#pragma unroll
            for (int dd = 0; dd < 16; dd++) a += vs[j * 16 + dd] * Ws[k * 32 + j * 16 + dd];
            g[tid] += a;
        }
        __syncthreads();
    }

    if (tid < 2) {
        float s2 = 1e-8f;
#pragma unroll
        for (int dd = 0; dd < 16; dd++) { const float t = vs[tid * 16 + dd]; s2 += t * t; }
        out[b * 2 + tid] = sqrtf(s2);
    }
}

// ---------------------------------------------------------------------------
extern "C" void kernel_launch(void* const* d_in, const int* in_sizes, int n_in,
                              void* d_out, int out_size) {
    const float* x      = (const float*)d_in[0];
    const float* conv_w = (const float*)d_in[1];
    const float* conv_b = (const float*)d_in[2];
    const float* ca_w1  = (const float*)d_in[3];
    const float* ca_w2  = (const float*)d_in[4];
    const float* sa_w   = (const float*)d_in[5];
    const float* caps_W = (const float*)d_in[6];
    float* out = (float*)d_out;

    k_conv<<<dim3(CC, BB), 256>>>(x, conv_w, conv_b);
    k_ca<<<BB, 64>>>(ca_w1, ca_w2);
    k_spatial<<<BB, 512>>>(sa_w);
    k_routing<<<BB, 512>>>(caps_W, out);
}